// round 11
// baseline (speedup 1.0000x reference)
#include <cuda_runtime.h>
#include <math.h>

#define NN 4096
#define EE 65536
#define CDIV(a,b) (((a)+(b)-1)/(b))

// ---- static scratch (floats) ----
constexpr int O_AP0 =0;
constexpr int O_AP1 =O_AP0+820*820;
constexpr int O_AP2 =O_AP1+164*164;
constexpr int O_AP3 =O_AP2+33*33;
constexpr int O_AP4 =O_AP3+7*7;
constexpr int O_L   =O_AP4+2*2;          // 164 x 820
constexpr int O_R   =O_L+164*820;        // 820 x 164
constexpr int O_PQ  =O_R+820*164;        // 4096 x 256 (P | Q)
constexpr int O_H1  =O_PQ+4096*256;
constexpr int O_Z   =O_H1+4096*128;
constexpr int O_X0  =O_Z+4096*128;
constexpr int O_XS1 =O_X0+4096*128;
constexpr int O_XS2 =O_XS1+820*128;
constexpr int O_XS3 =O_XS2+164*128;
constexpr int O_XS4 =O_XS3+33*128;
constexpr int O_XBOT=O_XS4+7*128;
constexpr int O_XP  =O_XBOT+2*128;       // up ping
constexpr int O_XB  =O_XP+820*128;       // up pong
constexpr int O_UNET=O_XB+820*128;
constexpr int O_F   =O_UNET+4096*128;
constexpr int O_Z4  =O_F+4096*4;
constexpr int O_SC  =O_Z4+4096*4;
constexpr int O_SV  =O_SC+4096;
constexpr int O_PD  =O_SV+1032;
constexpr int O_DI2 =O_PD+1032;
constexpr int O_DI1 =O_DI2+4096;
constexpr int O_CF  =O_DI1+4096;
constexpr int O_PN  =O_CF+4096;
constexpr int BUFSZ =O_PN+8;
__device__ float g_buf[BUFSZ];

constexpr int I_PTR=0, I_COL=4100, I_EID=I_COL+EE, I_CUR=I_EID+EE,
              I_CNT=I_CUR+4096, I_PERM=I_CNT+4096, I_POS=I_PERM+1032,
              IBUFSZ=I_POS+5120;
__device__ int g_ibuf[IBUFSZ];

// ---- setup kernels ----
__global__ void k_zero(float*p,int n){int i=blockIdx.x*blockDim.x+threadIdx.x;if(i<n)p[i]=0.f;}
__global__ void k_iset(int*p,int n,int v){int i=blockIdx.x*blockDim.x+threadIdx.x;if(i<n)p[i]=v;}
__global__ void k_icopy(int*d,const int*s,int n){int i=blockIdx.x*blockDim.x+threadIdx.x;if(i<n)d[i]=s[i];}
__global__ void k_count(const int*dst,int*cnt){int e=blockIdx.x*blockDim.x+threadIdx.x;if(e<EE)atomicAdd(&cnt[dst[e]],1);}
// exclusive scan of 4096 ints, warp-shuffle
__global__ void k_scan(const int*__restrict__ cnt,int*__restrict__ ptr){
    __shared__ int ws[32];
    int t=threadIdx.x,lane=t&31,warp=t>>5;
    int4 c=((const int4*)cnt)[t];
    int s0=c.x,s1=s0+c.y,s2=s1+c.z,s3=s2+c.w;
    int v=s3;
    #pragma unroll
    for(int o=1;o<32;o<<=1){int u=__shfl_up_sync(0xffffffffu,v,o);if(lane>=o)v+=u;}
    if(lane==31)ws[warp]=v;
    __syncthreads();
    if(warp==0){
        int w=ws[lane];
        #pragma unroll
        for(int o=1;o<32;o<<=1){int u=__shfl_up_sync(0xffffffffu,w,o);if(lane>=o)w+=u;}
        ws[lane]=w;
    }
    __syncthreads();
    int base=(warp?ws[warp-1]:0)+v-s3;
    ptr[4*t+1]=base+s0;ptr[4*t+2]=base+s1;ptr[4*t+3]=base+s2;ptr[4*t+4]=base+s3;
    if(t==0)ptr[0]=0;
}
__global__ void k_fillcsr(const int*src,const int*dst,int*cur,int*col,int*eid){
    int e=blockIdx.x*blockDim.x+threadIdx.x;
    if(e<EE){int d=dst[e];int p=atomicAdd(&cur[d],1);col[p]=src[e];eid[p]=e;}
}
__global__ void k_dinv(const int*cnt,float*d2,float*d1,float*cf){
    int i=blockIdx.x*blockDim.x+threadIdx.x;
    if(i<NN){float c=(float)cnt[i];d2[i]=rsqrtf(c+2.f);d1[i]=rsqrtf(c+1.f);cf[i]=c;}
}
__global__ void k_pnorm(const float*pw,float*pn){
    __shared__ float r[128]; int tid=threadIdx.x;
    for(int l=0;l<5;l++){
        float v=pw[l*128+tid];r[tid]=v*v;__syncthreads();
        for(int s=64;s>0;s>>=1){if(tid<s)r[tid]+=r[tid+s];__syncthreads();}
        if(tid==0)pn[l]=sqrtf(r[0]);
        __syncthreads();
    }
}

// ---- fused GEMM: C = rs ⊙ (op(A)@op(B) + fill*D) + bias, relu ----
// AM: 0 plain | 1 row-gather*scale | 2 row-add (pos/up) | 3 node-attr compose | 4 cat(H1,relu(UNET))
// BM: 0 plain | 1 dual (gn<128 ? B : B2)
template<int AM,int BM>
__global__ void __launch_bounds__(256) k_gemmT(
        const float*__restrict__ A,const float*__restrict__ B,const float*__restrict__ B2,
        float*__restrict__ C,int M,int N,int K,
        const float*__restrict__ rs,const float*__restrict__ bias,int relu,
        const float*__restrict__ Dm,float fill,
        const int*__restrict__ aidx,const float*__restrict__ aux,const float*__restrict__ aux2){
    __shared__ float As[16][65], Bs[16][64];
    int tx=threadIdx.x,ty=threadIdx.y,tid=ty*16+tx;
    int m0=blockIdx.y*64,n0=blockIdx.x*64;
    float acc[4][4]={};
    for(int k0=0;k0<K;k0+=16){
        #pragma unroll
        for(int l=0;l<4;l++){int lin=tid+l*256;int m=lin>>4,kk=lin&15;
            int gm=m0+m,gk=k0+kk;float v=0.f;
            if(gm<M&&gk<K){
                if(AM==0)v=A[gm*K+gk];
                else if(AM==1)v=A[aidx[gm]*K+gk]*aux[gm];
                else if(AM==2){v=A[gm*K+gk];int p=aidx[gm];if(p>=0)v+=aux[p*K+gk];}
                else if(AM==3)v=(gk<4)?A[gm*4+gk]:(gk<12?aux[gm*8+gk-4]:aux2[gm*128+gk-12]);
                else if(AM==4)v=(gk<128)?A[gm*128+gk]:fmaxf(aux[gm*128+gk-128],0.f);
            }
            As[kk][m]=v;}
        #pragma unroll
        for(int l=0;l<4;l++){int lin=tid+l*256;int kk=lin>>6,nn=lin&63;
            int gk=k0+kk,gn=n0+nn;float v=0.f;
            if(gk<K&&gn<N){
                if(BM==0)v=B[gk*N+gn];
                else v=(gn<128)?B[gk*128+gn]:B2[gk*128+gn-128];
            }
            Bs[kk][nn]=v;}
        __syncthreads();
        #pragma unroll
        for(int kk=0;kk<16;kk++){
            float a[4],b[4];
            #pragma unroll
            for(int i=0;i<4;i++)a[i]=As[kk][ty*4+i];
            #pragma unroll
            for(int j=0;j<4;j++)b[j]=Bs[kk][tx*4+j];
            #pragma unroll
            for(int i=0;i<4;i++)
                #pragma unroll
                for(int j=0;j<4;j++)acc[i][j]+=a[i]*b[j];
        }
        __syncthreads();
    }
    #pragma unroll
    for(int i=0;i<4;i++){
        int r=m0+ty*4+i;if(r>=M)continue;
        float sc=rs?rs[r]:1.f;
        #pragma unroll
        for(int j=0;j<4;j++){
            int c=n0+tx*4+j;if(c>=N)continue;
            float v=acc[i][j];
            if(Dm)v+=fill*Dm[r*N+c];
            v*=sc;
            if(bias)v+=bias[c];
            if(relu)v=fmaxf(v,0.f);
            C[r*N+c]=v;
        }
    }
}

// message aggregation + relu(h1). P/Q packed in PQ (stride 256).
__global__ void k_h1m(const int*__restrict__ ptr,const int*__restrict__ col,
                      const int*__restrict__ eid,const float*__restrict__ me,
                      const float*__restrict__ Wm,const float*__restrict__ PQ,
                      const float*__restrict__ bm,const float*__restrict__ cf,float*h1){
    __shared__ float wb[512];
    int d=blockIdx.x,h=threadIdx.x;
    const float*Wb=Wm+280*128;
    for(int i=h;i<512;i+=128)wb[i]=Wb[i];
    __syncthreads();
    float s=0.f;
    int e0=ptr[d],e1=ptr[d+1];
    for(int i=e0;i<e1;i++){
        int c=col[i],e=eid[i];
        s+=PQ[c*256+128+h]+me[e*4]*wb[h]+me[e*4+1]*wb[128+h]+me[e*4+2]*wb[256+h]+me[e*4+3]*wb[384+h];
    }
    h1[d*128+h]=fmaxf(s+cf[d]*(PQ[d*256+h]+bm[h]),0.f);
}
// CSR spmm + gcn epilogue
__global__ void k_spmmgcn(const int*__restrict__ ptr,const int*__restrict__ col,
                          const float*__restrict__ z,const float*__restrict__ dinv,
                          const float*__restrict__ bias,float fill,int relu,float*out){
    int d=blockIdx.x,h=threadIdx.x;
    float s=0.f;
    int e0=ptr[d],e1=ptr[d+1];
    for(int i=e0;i<e1;i++)s+=z[col[i]*128+h];
    float v=dinv[d]*(s+fill*z[d*128+h])+bias[h];
    out[d*128+h]=relu?fmaxf(v,0.f):v;
}
// grid-parallel score
__global__ void k_score(const float*__restrict__ x,const float*__restrict__ w,
                        const float*__restrict__ pn,int l,float*sc){
    __shared__ float r[128]; int n=blockIdx.x,tid=threadIdx.x;
    r[tid]=x[n*128+tid]*w[tid];__syncthreads();
    for(int s=64;s>0;s>>=1){if(tid<s)r[tid]+=r[tid+s];__syncthreads();}
    if(tid==0)sc[n]=tanhf(r[0]/pn[l]);
}
// single-block bitonic sort + perm/sv/pos. desc by value, ties -> lower index.
__global__ void k_topk(const float*__restrict__ sc,int n,int pad,int k,
                       int*perm,float*sv,int*pos){
    __shared__ float v[4096]; __shared__ int id[4096];
    int tid=threadIdx.x;
    for(int i=tid;i<pad;i+=1024){v[i]=(i<n)?sc[i]:-3.4e38f;id[i]=(i<n)?i:0x7fffffff;}
    __syncthreads();
    for(int ks=2;ks<=pad;ks<<=1){
        for(int j=ks>>1;j>0;j>>=1){
            for(int i=tid;i<pad;i+=1024){
                int ixj=i^j;
                if(ixj>i){
                    bool up=((i&ks)==0);
                    float va=v[ixj],vb=v[i];int ia=id[ixj],ib=id[i];
                    bool pre=(va>vb)||(va==vb&&ia<ib);
                    if(pre==up){v[ixj]=vb;v[i]=va;id[ixj]=ib;id[i]=ia;}
                }
            }
            __syncthreads();
        }
    }
    for(int i=tid;i<pad;i+=1024){
        int d=id[i];
        if(i<k){perm[i]=d;sv[i]=v[i];}
        if(d<n)pos[d]=(i<k)?i:-1;
    }
}
// level-0 restricted augment: shared-row two-hop; fuses zero+atomics+diag+rowsum(pd)
__global__ void k_ap0(const int*__restrict__ perm,const int*__restrict__ ptr,
                      const int*__restrict__ col,const int*__restrict__ pos,
                      float*__restrict__ ap,float*__restrict__ pd){
    __shared__ float row[820];
    __shared__ float red[4];
    int a=blockIdx.x,pa=perm[a];
    int tid=threadIdx.x,lane=tid&31,warp=tid>>5;
    for(int b=tid;b<820;b+=128)row[b]=0.f;
    __syncthreads();
    int beg=ptr[pa],end=ptr[pa+1];
    for(int i1=beg+warp;i1<end;i1+=4){
        int c1=col[i1];
        if(c1==pa)continue;
        if(lane==0){int b=pos[c1];if(b>=0)atomicAdd(&row[b],2.f);}
        int b2=ptr[c1],e2=ptr[c1+1];
        for(int i2=b2+lane;i2<e2;i2+=32){
            int c2=col[i2];
            if(c2==c1)continue;
            int b=pos[c2];
            if(b>=0)atomicAdd(&row[b],1.f);
        }
    }
    __syncthreads();
    if(tid==0)row[a]=0.f;
    __syncthreads();
    float s=0.f;
    for(int b=tid;b<820;b+=128)s+=row[b];
    #pragma unroll
    for(int o=16;o>0;o>>=1)s+=__shfl_xor_sync(0xffffffffu,s,o);
    if(lane==0)red[warp]=s;
    __syncthreads();
    if(tid==0)pd[a]=rsqrtf(red[0]+red[1]+red[2]+red[3]+2.f);
    for(int b=tid;b<820;b+=128)ap[a*820+b]=row[b];
}
// L[m x n]: row a = A1[perm[a], :];  R[n x m]: col b = A1[:, perm[b]]
__global__ void k_gLR(const float*__restrict__ Ap,int n,const int*__restrict__ perm,int m,
                      float*__restrict__ L,float*__restrict__ R){
    int i=blockIdx.x*blockDim.x+threadIdx.x;
    if(i<m*n){int a=i/n,k=i-a*n;int pa=perm[a];L[i]=(k==pa)?1.f:Ap[pa*n+k];}
    if(i<n*m){int k=i/m,b=i-k*m;int pb=perm[b];R[i]=(k==pb)?1.f:Ap[k*n+pb];}
}
// zero diag + row-sum -> pd (levels >= 1)
__global__ void k_rowdinv(float*ap,int m,float*pd){
    int a=blockIdx.x*blockDim.x+threadIdx.x;
    if(a<m){
        ap[a*m+a]=0.f;
        float s=0.f;
        for(int b=0;b<m;b++)s+=ap[a*m+b];
        pd[a]=rsqrtf(s+2.f);
    }
}
__global__ void k_fout(const int*__restrict__ ptr,const int*__restrict__ col,
                       const float*__restrict__ z4,const float*__restrict__ d1,
                       const float*__restrict__ bo,float*Fb,float*out,int t){
    int i=blockIdx.x*blockDim.x+threadIdx.x;
    if(i<NN*4){int d=i>>2,f=i&3;
        float s=0.f;
        int e0=ptr[d],e1=ptr[d+1];
        for(int j=e0;j<e1;j++)s+=z4[col[j]*4+f];
        float v=d1[d]*(s+z4[i])+bo[f];
        Fb[i]=v;out[d*8+t*4+f]=v;}
}

// ---- host ----
template<int AM,int BM>
static void gemmT(const float*A,const float*B,const float*B2,float*C,int M,int N,int K,
                  const float*rs,const float*bias,int relu,const float*Dm,float fill,
                  const int*aidx,const float*aux,const float*aux2){
    dim3 b(16,16),g(CDIV(N,64),CDIV(M,64));
    k_gemmT<AM,BM><<<g,b>>>(A,B,B2,C,M,N,K,rs,bias,relu,Dm,fill,aidx,aux,aux2);
}

extern "C" void kernel_launch(void* const* d_in, const int* in_sizes, int n_in,
                              void* d_out, int out_size){
    const float*F0 =(const float*)d_in[0];
    const float*mn =(const float*)d_in[1];
    const float*me =(const float*)d_in[2];
    const float*Wm =(const float*)d_in[3];
    const float*bm =(const float*)d_in[4];
    const float*Wd0=(const float*)d_in[5];
    const float*bd0=(const float*)d_in[6];
    const float*Wd =(const float*)d_in[7];
    const float*bd =(const float*)d_in[8];
    const float*pw =(const float*)d_in[9];
    const float*Wu =(const float*)d_in[10];
    const float*bu =(const float*)d_in[11];
    const float*Wo =(const float*)d_in[12];
    const float*bo =(const float*)d_in[13];
    const int*ei   =(const int*)d_in[14];
    const int*src=ei,*dst=ei+EE;
    float*out=(float*)d_out;

    float*buf;int*ib;
    cudaGetSymbolAddress((void**)&buf,g_buf);
    cudaGetSymbolAddress((void**)&ib,g_ibuf);

    const int NS[6]={4096,820,164,33,7,2};
    const int KL[5]={820,164,33,7,2};
    const int POFF[5]={0,820,984,1017,1024};       // perm / sv / pd offsets
    const int QOFF[5]={0,4096,4916,5080,5113};     // pos offsets
    const int PAD[5]={4096,1024,256,64,8};
    float* AP[5]={buf+O_AP0,buf+O_AP1,buf+O_AP2,buf+O_AP3,buf+O_AP4};
    float* XL[6]={buf+O_X0,buf+O_XS1,buf+O_XS2,buf+O_XS3,buf+O_XS4,buf+O_XBOT};
    float*PQ=buf+O_PQ,*H1=buf+O_H1,*Z=buf+O_Z;
    float*XP=buf+O_XP,*XB=buf+O_XB,*UNET=buf+O_UNET;
    float*FB=buf+O_F,*Z4=buf+O_Z4,*SC=buf+O_SC;
    float*SV=buf+O_SV,*PD=buf+O_PD,*D2=buf+O_DI2,*D1=buf+O_DI1,*CF=buf+O_CF,*PN=buf+O_PN;
    float*Lb=buf+O_L,*Rb=buf+O_R;
    int*PTR=ib+I_PTR,*COL=ib+I_COL,*EID=ib+I_EID,*CUR=ib+I_CUR,*CNT=ib+I_CNT,
       *PERM=ib+I_PERM,*POS=ib+I_POS;

    // one-time setup
    k_zero<<<CDIV(NN*128,256),256>>>(UNET,NN*128);
    k_iset<<<CDIV(NN,256),256>>>(CNT,NN,0);
    k_count<<<CDIV(EE,256),256>>>(dst,CNT);
    k_scan<<<1,1024>>>(CNT,PTR);
    k_icopy<<<CDIV(NN,256),256>>>(CUR,PTR,NN);
    k_fillcsr<<<CDIV(EE,256),256>>>(src,dst,CUR,COL,EID);
    k_dinv<<<CDIV(NN,256),256>>>(CNT,D2,D1,CF);
    k_pnorm<<<1,128>>>(pw,PN);

    for(int t=0;t<2;t++){
        const float*Fc=(t==0)?F0:FB;
        // fused node-attr compose + P|Q GEMM
        gemmT<3,1>(Fc,Wm,Wm+140*128,PQ,NN,256,140,0,0,0,0,0.f,0,mn,UNET);
        k_h1m<<<NN,128>>>(PTR,COL,EID,me,Wm,PQ,bm,CF,H1);
        // unet down-0 gcn (fill=2, relu)
        gemmT<0,0>(H1,Wd0,0,Z,NN,128,128,D2,0,0,0,0.f,0,0,0);
        k_spmmgcn<<<NN,128>>>(PTR,COL,Z,D2,bd0,2.f,1,XL[0]);
        // down levels
        for(int i=0;i<5;i++){
            int n=NS[i],k=KL[i];
            k_score<<<n,128>>>(XL[i],pw+i*128,PN,i,SC);
            k_topk<<<1,1024>>>(SC,n,PAD[i],k,PERM+POFF[i],SV+POFF[i],POS+QOFF[i]);
            if(i==0){
                k_ap0<<<820,128>>>(PERM,PTR,COL,POS,AP[0],PD);
            }else{
                k_gLR<<<CDIV(k*n,256),256>>>(AP[i-1],n,PERM+POFF[i],k,Lb,Rb);
                gemmT<0,0>(Lb,Rb,0,AP[i],k,k,n,0,0,0,0,0.f,0,0,0);
                k_rowdinv<<<CDIV(k,64),64>>>(AP[i],k,PD+POFF[i]);
            }
            // Z = PD ⊙ (gather(x)*sv @ Wd)
            gemmT<1,0>(XL[i],Wd+i*16384,0,Z,k,128,128,PD+POFF[i],0,0,0,0.f,
                       PERM+POFF[i],SV+POFF[i],0);
            // x_{i+1} = relu(PD ⊙ (AP@Z + 2Z) + bd)
            gemmT<0,0>(AP[i],Z,0,XL[i+1],k,128,k,PD+POFF[i],bd+i*128,1,Z,2.f,0,0,0);
        }
        // up levels
        float*xin=XL[5];
        for(int i=0;i<5;i++){
            int j=4-i;
            if(j>0){
                int nj=NS[j];
                gemmT<2,0>(XL[j],Wu+i*16384,0,Z,nj,128,128,PD+POFF[j-1],0,0,0,0.f,
                           POS+QOFF[j],xin,0);
                float*xo=(i%2==0)?XB:XP;
                gemmT<0,0>(AP[j-1],Z,0,xo,nj,128,nj,PD+POFF[j-1],bu+i*128,1,Z,2.f,0,0,0);
                xin=xo;
            }else{
                gemmT<2,0>(XL[0],Wu+4*16384,0,Z,NN,128,128,D2,0,0,0,0.f,POS,xin,0);
                k_spmmgcn<<<NN,128>>>(PTR,COL,Z,D2,bu+4*128,2.f,0,UNET);
            }
        }
        // output gcn (fill=1), cat fused into A loader
        gemmT<4,0>(H1,Wo,0,Z4,NN,4,256,D1,0,0,0,0.f,0,UNET,0);
        k_fout<<<CDIV(NN*4,256),256>>>(PTR,COL,Z4,D1,bo,FB,out,t);
    }
}

// round 13
// speedup vs baseline: 1.1860x; 1.1860x over previous
#include <cuda_runtime.h>
#include <math.h>

#define NN 4096
#define EE 65536
#define CDIV(a,b) (((a)+(b)-1)/(b))

// ---- static scratch (floats) ----
constexpr int O_AP0 =0;
constexpr int O_AP1 =O_AP0+820*820;
constexpr int O_AP2 =O_AP1+164*164;
constexpr int O_AP3 =O_AP2+33*33;
constexpr int O_AP4 =O_AP3+7*7;
constexpr int O_L   =O_AP4+2*2;          // 164 x 820
constexpr int O_R   =O_L+164*820;        // 820 x 164
constexpr int O_PQ  =O_R+820*164;        // 4096 x 256 (P | Q)
constexpr int O_H1  =O_PQ+4096*256;
constexpr int O_Z   =O_H1+4096*128;
constexpr int O_X0  =O_Z+4096*128;
constexpr int O_XS1 =O_X0+4096*128;
constexpr int O_XS2 =O_XS1+820*128;
constexpr int O_XS3 =O_XS2+164*128;
constexpr int O_XS4 =O_XS3+33*128;
constexpr int O_XBOT=O_XS4+7*128;
constexpr int O_XP  =O_XBOT+2*128;       // up ping
constexpr int O_XB  =O_XP+820*128;       // up pong
constexpr int O_UNET=O_XB+820*128;
constexpr int O_F   =O_UNET+4096*128;
constexpr int O_Z4  =O_F+4096*4;
constexpr int O_SC  =O_Z4+4096*4;
constexpr int O_SV  =O_SC+4096;
constexpr int O_PD  =O_SV+1032;
constexpr int O_DI2 =O_PD+1032;
constexpr int O_DI1 =O_DI2+4096;
constexpr int O_CF  =O_DI1+4096;
constexpr int O_PN  =O_CF+4096;
constexpr int BUFSZ =O_PN+8;
__device__ float g_buf[BUFSZ];

constexpr int I_PTR=0, I_COL=4100, I_EID=I_COL+EE, I_CUR=I_EID+EE,
              I_CNT=I_CUR+4096, I_PERM=I_CNT+4096, I_POS=I_PERM+1032,
              IBUFSZ=I_POS+5120;
__device__ int g_ibuf[IBUFSZ];

// ---- setup kernels ----
__global__ void k_zero(float*p,int n){int i=blockIdx.x*blockDim.x+threadIdx.x;if(i<n)p[i]=0.f;}
__global__ void k_iset(int*p,int n,int v){int i=blockIdx.x*blockDim.x+threadIdx.x;if(i<n)p[i]=v;}
__global__ void k_icopy(int*d,const int*s,int n){int i=blockIdx.x*blockDim.x+threadIdx.x;if(i<n)d[i]=s[i];}
__global__ void k_count(const int*dst,int*cnt){int e=blockIdx.x*blockDim.x+threadIdx.x;if(e<EE)atomicAdd(&cnt[dst[e]],1);}
__global__ void k_scan(const int*__restrict__ cnt,int*__restrict__ ptr){
    __shared__ int ws[32];
    int t=threadIdx.x,lane=t&31,warp=t>>5;
    int4 c=((const int4*)cnt)[t];
    int s0=c.x,s1=s0+c.y,s2=s1+c.z,s3=s2+c.w;
    int v=s3;
    #pragma unroll
    for(int o=1;o<32;o<<=1){int u=__shfl_up_sync(0xffffffffu,v,o);if(lane>=o)v+=u;}
    if(lane==31)ws[warp]=v;
    __syncthreads();
    if(warp==0){
        int w=ws[lane];
        #pragma unroll
        for(int o=1;o<32;o<<=1){int u=__shfl_up_sync(0xffffffffu,w,o);if(lane>=o)w+=u;}
        ws[lane]=w;
    }
    __syncthreads();
    int base=(warp?ws[warp-1]:0)+v-s3;
    ptr[4*t+1]=base+s0;ptr[4*t+2]=base+s1;ptr[4*t+3]=base+s2;ptr[4*t+4]=base+s3;
    if(t==0)ptr[0]=0;
}
__global__ void k_fillcsr(const int*src,const int*dst,int*cur,int*col,int*eid){
    int e=blockIdx.x*blockDim.x+threadIdx.x;
    if(e<EE){int d=dst[e];int p=atomicAdd(&cur[d],1);col[p]=src[e];eid[p]=e;}
}
__global__ void k_dinv(const int*cnt,float*d2,float*d1,float*cf){
    int i=blockIdx.x*blockDim.x+threadIdx.x;
    if(i<NN){float c=(float)cnt[i];d2[i]=rsqrtf(c+2.f);d1[i]=rsqrtf(c+1.f);cf[i]=c;}
}
__global__ void k_pnorm(const float*pw,float*pn){
    __shared__ float r[128]; int tid=threadIdx.x;
    for(int l=0;l<5;l++){
        float v=pw[l*128+tid];r[tid]=v*v;__syncthreads();
        for(int s=64;s>0;s>>=1){if(tid<s)r[tid]+=r[tid+s];__syncthreads();}
        if(tid==0)pn[l]=sqrtf(r[0]);
        __syncthreads();
    }
}

// ---- fused GEMM: C = rs ⊙ (op(A)@op(B) + fill*D) + bias, relu ----
// AM: 0 plain | 1 row-gather*scale | 2 row-add (pos/up) | 3 node-attr compose | 4 cat(H1,relu(UNET))
// BMo: 0 plain | 1 dual (gn<128 ? B : B2)
// TM: 128 (256 thr) or 64 (128 thr); TN=64; TK=16; micro-tile 8x4 per thread.
template<int AM,int BMo,int TM>
__global__ void __launch_bounds__(TM*2) k_gemmT(
        const float*__restrict__ A,const float*__restrict__ B,const float*__restrict__ B2,
        float*__restrict__ C,int M,int N,int K,
        const float*__restrict__ rs,const float*__restrict__ bias,int relu,
        const float*__restrict__ Dm,float fill,
        const int*__restrict__ aidx,const float*__restrict__ aux,const float*__restrict__ aux2){
    constexpr int THREADS=TM*2;
    constexpr int AELEM=TM*16/THREADS;   // 8
    constexpr int BELEM=1024/THREADS;    // 4 (TM=128) or 8 (TM=64)
    __shared__ float As[16][TM+4];
    __shared__ float Bs[16][64];
    int tid=threadIdx.x;
    int tx=tid&15, ty=tid>>4;            // ty: 0..TM/8-1
    int m0=blockIdx.y*TM, n0=blockIdx.x*64;
    float acc[8][4]={};
    for(int k0=0;k0<K;k0+=16){
        #pragma unroll
        for(int l=0;l<AELEM;l++){
            int lin=tid+l*THREADS; int m=lin>>4, kk=lin&15;
            int gm=m0+m, gk=k0+kk; float v=0.f;
            if(gm<M&&gk<K){
                if(AM==0)v=A[gm*K+gk];
                else if(AM==1)v=A[aidx[gm]*K+gk]*aux[gm];
                else if(AM==2){v=A[gm*K+gk];int p=aidx[gm];if(p>=0)v+=aux[p*K+gk];}
                else if(AM==3)v=(gk<4)?A[gm*4+gk]:(gk<12?aux[gm*8+gk-4]:aux2[gm*128+gk-12]);
                else if(AM==4)v=(gk<128)?A[gm*128+gk]:fmaxf(aux[gm*128+gk-128],0.f);
            }
            As[kk][m]=v;
        }
        #pragma unroll
        for(int l=0;l<BELEM;l++){
            int lin=tid+l*THREADS; int kk=lin>>6, nn=lin&63;
            int gk=k0+kk, gn=n0+nn; float v=0.f;
            if(gk<K&&gn<N){
                if(BMo==0)v=B[gk*N+gn];
                else v=(gn<128)?B[gk*128+gn]:B2[gk*128+gn-128];
            }
            Bs[kk][nn]=v;
        }
        __syncthreads();
        #pragma unroll
        for(int kk=0;kk<16;kk++){
            const float4* a4=reinterpret_cast<const float4*>(&As[kk][ty*8]);
            float4 a0=a4[0], a1=a4[1];
            float4 bv=*reinterpret_cast<const float4*>(&Bs[kk][tx*4]);
            float a[8]={a0.x,a0.y,a0.z,a0.w,a1.x,a1.y,a1.z,a1.w};
            float b[4]={bv.x,bv.y,bv.z,bv.w};
            #pragma unroll
            for(int i=0;i<8;i++)
                #pragma unroll
                for(int j=0;j<4;j++)acc[i][j]+=a[i]*b[j];
        }
        __syncthreads();
    }
    #pragma unroll
    for(int i=0;i<8;i++){
        int r=m0+ty*8+i; if(r>=M)continue;
        float sc=rs?rs[r]:1.f;
        #pragma unroll
        for(int j=0;j<4;j++){
            int c=n0+tx*4+j; if(c>=N)continue;
            float v=acc[i][j];
            if(Dm)v+=fill*Dm[r*N+c];
            v*=sc;
            if(bias)v+=bias[c];
            if(relu)v=fmaxf(v,0.f);
            C[r*N+c]=v;
        }
    }
}

// message aggregation + relu(h1). P/Q packed in PQ (stride 256).
__global__ void k_h1m(const int*__restrict__ ptr,const int*__restrict__ col,
                      const int*__restrict__ eid,const float*__restrict__ me,
                      const float*__restrict__ Wm,const float*__restrict__ PQ,
                      const float*__restrict__ bm,const float*__restrict__ cf,float*h1){
    __shared__ float wb[512];
    int d=blockIdx.x,h=threadIdx.x;
    const float*Wb=Wm+280*128;
    for(int i=h;i<512;i+=128)wb[i]=Wb[i];
    __syncthreads();
    float s=0.f;
    int e0=ptr[d],e1=ptr[d+1];
    for(int i=e0;i<e1;i++){
        int c=col[i],e=eid[i];
        s+=PQ[c*256+128+h]+me[e*4]*wb[h]+me[e*4+1]*wb[128+h]+me[e*4+2]*wb[256+h]+me[e*4+3]*wb[384+h];
    }
    h1[d*128+h]=fmaxf(s+cf[d]*(PQ[d*256+h]+bm[h]),0.f);
}
// CSR spmm + gcn epilogue
__global__ void k_spmmgcn(const int*__restrict__ ptr,const int*__restrict__ col,
                          const float*__restrict__ z,const float*__restrict__ dinv,
                          const float*__restrict__ bias,float fill,int relu,float*out){
    int d=blockIdx.x,h=threadIdx.x;
    float s=0.f;
    int e0=ptr[d],e1=ptr[d+1];
    for(int i=e0;i<e1;i++)s+=z[col[i]*128+h];
    float v=dinv[d]*(s+fill*z[d*128+h])+bias[h];
    out[d*128+h]=relu?fmaxf(v,0.f):v;
}
// grid-parallel score
__global__ void k_score(const float*__restrict__ x,const float*__restrict__ w,
                        const float*__restrict__ pn,int l,float*sc){
    __shared__ float r[128]; int n=blockIdx.x,tid=threadIdx.x;
    r[tid]=x[n*128+tid]*w[tid];__syncthreads();
    for(int s=64;s>0;s>>=1){if(tid<s)r[tid]+=r[tid+s];__syncthreads();}
    if(tid==0)sc[n]=tanhf(r[0]/pn[l]);
}
// single-block bitonic sort + perm/sv/pos. desc by value, ties -> lower index.
__global__ void k_topk(const float*__restrict__ sc,int n,int pad,int k,
                       int*perm,float*sv,int*pos){
    __shared__ float v[4096]; __shared__ int id[4096];
    int tid=threadIdx.x;
    for(int i=tid;i<pad;i+=1024){v[i]=(i<n)?sc[i]:-3.4e38f;id[i]=(i<n)?i:0x7fffffff;}
    __syncthreads();
    for(int ks=2;ks<=pad;ks<<=1){
        for(int j=ks>>1;j>0;j>>=1){
            for(int i=tid;i<pad;i+=1024){
                int ixj=i^j;
                if(ixj>i){
                    bool up=((i&ks)==0);
                    float va=v[ixj],vb=v[i];int ia=id[ixj],ib=id[i];
                    bool pre=(va>vb)||(va==vb&&ia<ib);
                    if(pre==up){v[ixj]=vb;v[i]=va;id[ixj]=ib;id[i]=ia;}
                }
            }
            __syncthreads();
        }
    }
    for(int i=tid;i<pad;i+=1024){
        int d=id[i];
        if(i<k){perm[i]=d;sv[i]=v[i];}
        if(d<n)pos[d]=(i<k)?i:-1;
    }
}
// level-0 restricted augment: shared-row two-hop; fuses zero+atomics+diag+rowsum(pd)
__global__ void k_ap0(const int*__restrict__ perm,const int*__restrict__ ptr,
                      const int*__restrict__ col,const int*__restrict__ pos,
                      float*__restrict__ ap,float*__restrict__ pd){
    __shared__ float row[820];
    __shared__ float red[4];
    int a=blockIdx.x,pa=perm[a];
    int tid=threadIdx.x,lane=tid&31,warp=tid>>5;
    for(int b=tid;b<820;b+=128)row[b]=0.f;
    __syncthreads();
    int beg=ptr[pa],end=ptr[pa+1];
    for(int i1=beg+warp;i1<end;i1+=4){
        int c1=col[i1];
        if(c1==pa)continue;
        if(lane==0){int b=pos[c1];if(b>=0)atomicAdd(&row[b],2.f);}
        int b2=ptr[c1],e2=ptr[c1+1];
        for(int i2=b2+lane;i2<e2;i2+=32){
            int c2=col[i2];
            if(c2==c1)continue;
            int b=pos[c2];
            if(b>=0)atomicAdd(&row[b],1.f);
        }
    }
    __syncthreads();
    if(tid==0)row[a]=0.f;
    __syncthreads();
    float s=0.f;
    for(int b=tid;b<820;b+=128)s+=row[b];
    #pragma unroll
    for(int o=16;o>0;o>>=1)s+=__shfl_xor_sync(0xffffffffu,s,o);
    if(lane==0)red[warp]=s;
    __syncthreads();
    if(tid==0)pd[a]=rsqrtf(red[0]+red[1]+red[2]+red[3]+2.f);
    for(int b=tid;b<820;b+=128)ap[a*820+b]=row[b];
}
// L[m x n]: row a = A1[perm[a], :];  R[n x m]: col b = A1[:, perm[b]]
__global__ void k_gLR(const float*__restrict__ Ap,int n,const int*__restrict__ perm,int m,
                      float*__restrict__ L,float*__restrict__ R){
    int i=blockIdx.x*blockDim.x+threadIdx.x;
    if(i<m*n){int a=i/n,k=i-a*n;int pa=perm[a];L[i]=(k==pa)?1.f:Ap[pa*n+k];}
    if(i<n*m){int k=i/m,b=i-k*m;int pb=perm[b];R[i]=(k==pb)?1.f:Ap[k*n+pb];}
}
// zero diag + row-sum -> pd (levels >= 1)
__global__ void k_rowdinv(float*ap,int m,float*pd){
    int a=blockIdx.x*blockDim.x+threadIdx.x;
    if(a<m){
        ap[a*m+a]=0.f;
        float s=0.f;
        for(int b=0;b<m;b++)s+=ap[a*m+b];
        pd[a]=rsqrtf(s+2.f);
    }
}
__global__ void k_fout(const int*__restrict__ ptr,const int*__restrict__ col,
                       const float*__restrict__ z4,const float*__restrict__ d1,
                       const float*__restrict__ bo,float*Fb,float*out,int t){
    int i=blockIdx.x*blockDim.x+threadIdx.x;
    if(i<NN*4){int d=i>>2,f=i&3;
        float s=0.f;
        int e0=ptr[d],e1=ptr[d+1];
        for(int j=e0;j<e1;j++)s+=z4[col[j]*4+f];
        float v=d1[d]*(s+z4[i])+bo[f];
        Fb[i]=v;out[d*8+t*4+f]=v;}
}

// ---- host ----
template<int AM,int BMo>
static void gemmT(const float*A,const float*B,const float*B2,float*C,int M,int N,int K,
                  const float*rs,const float*bias,int relu,const float*Dm,float fill,
                  const int*aidx,const float*aux,const float*aux2){
    if(M>=1024){
        dim3 g(CDIV(N,64),CDIV(M,128));
        k_gemmT<AM,BMo,128><<<g,256>>>(A,B,B2,C,M,N,K,rs,bias,relu,Dm,fill,aidx,aux,aux2);
    }else{
        dim3 g(CDIV(N,64),CDIV(M,64));
        k_gemmT<AM,BMo,64><<<g,128>>>(A,B,B2,C,M,N,K,rs,bias,relu,Dm,fill,aidx,aux,aux2);
    }
}

extern "C" void kernel_launch(void* const* d_in, const int* in_sizes, int n_in,
                              void* d_out, int out_size){
    const float*F0 =(const float*)d_in[0];
    const float*mn =(const float*)d_in[1];
    const float*me =(const float*)d_in[2];
    const float*Wm =(const float*)d_in[3];
    const float*bm =(const float*)d_in[4];
    const float*Wd0=(const float*)d_in[5];
    const float*bd0=(const float*)d_in[6];
    const float*Wd =(const float*)d_in[7];
    const float*bd =(const float*)d_in[8];
    const float*pw =(const float*)d_in[9];
    const float*Wu =(const float*)d_in[10];
    const float*bu =(const float*)d_in[11];
    const float*Wo =(const float*)d_in[12];
    const float*bo =(const float*)d_in[13];
    const int*ei   =(const int*)d_in[14];
    const int*src=ei,*dst=ei+EE;
    float*out=(float*)d_out;

    float*buf;int*ib;
    cudaGetSymbolAddress((void**)&buf,g_buf);
    cudaGetSymbolAddress((void**)&ib,g_ibuf);

    const int NS[6]={4096,820,164,33,7,2};
    const int KL[5]={820,164,33,7,2};
    const int POFF[5]={0,820,984,1017,1024};       // perm / sv / pd offsets
    const int QOFF[5]={0,4096,4916,5080,5113};     // pos offsets
    const int PAD[5]={4096,1024,256,64,8};
    float* AP[5]={buf+O_AP0,buf+O_AP1,buf+O_AP2,buf+O_AP3,buf+O_AP4};
    float* XL[6]={buf+O_X0,buf+O_XS1,buf+O_XS2,buf+O_XS3,buf+O_XS4,buf+O_XBOT};
    float*PQ=buf+O_PQ,*H1=buf+O_H1,*Z=buf+O_Z;
    float*XP=buf+O_XP,*XB=buf+O_XB,*UNET=buf+O_UNET;
    float*FB=buf+O_F,*Z4=buf+O_Z4,*SC=buf+O_SC;
    float*SV=buf+O_SV,*PD=buf+O_PD,*D2=buf+O_DI2,*D1=buf+O_DI1,*CF=buf+O_CF,*PN=buf+O_PN;
    float*Lb=buf+O_L,*Rb=buf+O_R;
    int*PTR=ib+I_PTR,*COL=ib+I_COL,*EID=ib+I_EID,*CUR=ib+I_CUR,*CNT=ib+I_CNT,
       *PERM=ib+I_PERM,*POS=ib+I_POS;

    // one-time setup
    k_zero<<<CDIV(NN*128,256),256>>>(UNET,NN*128);
    k_iset<<<CDIV(NN,256),256>>>(CNT,NN,0);
    k_count<<<CDIV(EE,256),256>>>(dst,CNT);
    k_scan<<<1,1024>>>(CNT,PTR);
    k_icopy<<<CDIV(NN,256),256>>>(CUR,PTR,NN);
    k_fillcsr<<<CDIV(EE,256),256>>>(src,dst,CUR,COL,EID);
    k_dinv<<<CDIV(NN,256),256>>>(CNT,D2,D1,CF);
    k_pnorm<<<1,128>>>(pw,PN);

    for(int t=0;t<2;t++){
        const float*Fc=(t==0)?F0:FB;
        // fused node-attr compose + P|Q GEMM
        gemmT<3,1>(Fc,Wm,Wm+140*128,PQ,NN,256,140,0,0,0,0,0.f,0,mn,UNET);
        k_h1m<<<NN,128>>>(PTR,COL,EID,me,Wm,PQ,bm,CF,H1);
        // unet down-0 gcn (fill=2, relu)
        gemmT<0,0>(H1,Wd0,0,Z,NN,128,128,D2,0,0,0,0.f,0,0,0);
        k_spmmgcn<<<NN,128>>>(PTR,COL,Z,D2,bd0,2.f,1,XL[0]);
        // down levels
        for(int i=0;i<5;i++){
            int n=NS[i],k=KL[i];
            k_score<<<n,128>>>(XL[i],pw+i*128,PN,i,SC);
            k_topk<<<1,1024>>>(SC,n,PAD[i],k,PERM+POFF[i],SV+POFF[i],POS+QOFF[i]);
            if(i==0){
                k_ap0<<<820,128>>>(PERM,PTR,COL,POS,AP[0],PD);
            }else{
                k_gLR<<<CDIV(k*n,256),256>>>(AP[i-1],n,PERM+POFF[i],k,Lb,Rb);
                gemmT<0,0>(Lb,Rb,0,AP[i],k,k,n,0,0,0,0,0.f,0,0,0);
                k_rowdinv<<<CDIV(k,64),64>>>(AP[i],k,PD+POFF[i]);
            }
            // Z = PD ⊙ (gather(x)*sv @ Wd)
            gemmT<1,0>(XL[i],Wd+i*16384,0,Z,k,128,128,PD+POFF[i],0,0,0,0.f,
                       PERM+POFF[i],SV+POFF[i],0);
            // x_{i+1} = relu(PD ⊙ (AP@Z + 2Z) + bd)
            gemmT<0,0>(AP[i],Z,0,XL[i+1],k,128,k,PD+POFF[i],bd+i*128,1,Z,2.f,0,0,0);
        }
        // up levels
        float*xin=XL[5];
        for(int i=0;i<5;i++){
            int j=4-i;
            if(j>0){
                int nj=NS[j];
                gemmT<2,0>(XL[j],Wu+i*16384,0,Z,nj,128,128,PD+POFF[j-1],0,0,0,0.f,
                           POS+QOFF[j],xin,0);
                float*xo=(i%2==0)?XB:XP;
                gemmT<0,0>(AP[j-1],Z,0,xo,nj,128,nj,PD+POFF[j-1],bu+i*128,1,Z,2.f,0,0,0);
                xin=xo;
            }else{
                gemmT<2,0>(XL[0],Wu+4*16384,0,Z,NN,128,128,D2,0,0,0,0.f,POS,xin,0);
                k_spmmgcn<<<NN,128>>>(PTR,COL,Z,D2,bu+4*128,2.f,0,UNET);
            }
        }
        // output gcn (fill=1), cat fused into A loader
        gemmT<4,0>(H1,Wo,0,Z4,NN,4,256,D1,0,0,0,0.f,0,UNET,0);
        k_fout<<<CDIV(NN*4,256),256>>>(PTR,COL,Z4,D1,bo,FB,out,t);
    }
}

// round 14
// speedup vs baseline: 1.5866x; 1.3378x over previous
#include <cuda_runtime.h>
#include <math.h>

#define NN 4096
#define EE 65536
#define CDIV(a,b) (((a)+(b)-1)/(b))

// ---- static scratch (floats) ----
constexpr int O_AP0 =0;
constexpr int O_AP1 =O_AP0+820*820;
constexpr int O_AP2 =O_AP1+164*164;
constexpr int O_AP3 =O_AP2+33*33;
constexpr int O_AP4 =O_AP3+7*7;
constexpr int O_L   =O_AP4+2*2;          // 164 x 820
constexpr int O_R   =O_L+164*820;        // 820 x 164
constexpr int O_PQ  =O_R+820*164;        // 4096 x 256 (P | Q)
constexpr int O_H1  =O_PQ+4096*256;
constexpr int O_Z   =O_H1+4096*128;
constexpr int O_X0  =O_Z+4096*128;
constexpr int O_XS1 =O_X0+4096*128;
constexpr int O_XS2 =O_XS1+820*128;
constexpr int O_XS3 =O_XS2+164*128;
constexpr int O_XS4 =O_XS3+33*128;
constexpr int O_XBOT=O_XS4+7*128;
constexpr int O_XP  =O_XBOT+2*128;       // up ping
constexpr int O_XB  =O_XP+820*128;       // up pong
constexpr int O_UNET=O_XB+820*128;
constexpr int O_F   =O_UNET+4096*128;
constexpr int O_Z4  =O_F+4096*4;
constexpr int O_SC  =O_Z4+4096*4;
constexpr int O_SV  =O_SC+4096;
constexpr int O_PD  =O_SV+1032;
constexpr int O_DI2 =O_PD+1032;
constexpr int O_DI1 =O_DI2+4096;
constexpr int O_CF  =O_DI1+4096;
constexpr int O_PN  =O_CF+4096;
constexpr int BUFSZ =O_PN+8;
__device__ float g_buf[BUFSZ];

constexpr int I_PTR=0, I_COL=4100, I_EID=I_COL+EE, I_CUR=I_EID+EE,
              I_CNT=I_CUR+4096, I_PERM=I_CNT+4096, I_POS=I_PERM+1032,
              IBUFSZ=I_POS+5120;
__device__ int g_ibuf[IBUFSZ];

// ---- setup kernels ----
__global__ void k_zero(float*p,int n){int i=blockIdx.x*blockDim.x+threadIdx.x;if(i<n)p[i]=0.f;}
__global__ void k_iset(int*p,int n,int v){int i=blockIdx.x*blockDim.x+threadIdx.x;if(i<n)p[i]=v;}
__global__ void k_icopy(int*d,const int*s,int n){int i=blockIdx.x*blockDim.x+threadIdx.x;if(i<n)d[i]=s[i];}
__global__ void k_count(const int*dst,int*cnt){int e=blockIdx.x*blockDim.x+threadIdx.x;if(e<EE)atomicAdd(&cnt[dst[e]],1);}
__global__ void k_scan(const int*__restrict__ cnt,int*__restrict__ ptr){
    __shared__ int ws[32];
    int t=threadIdx.x,lane=t&31,warp=t>>5;
    int4 c=((const int4*)cnt)[t];
    int s0=c.x,s1=s0+c.y,s2=s1+c.z,s3=s2+c.w;
    int v=s3;
    #pragma unroll
    for(int o=1;o<32;o<<=1){int u=__shfl_up_sync(0xffffffffu,v,o);if(lane>=o)v+=u;}
    if(lane==31)ws[warp]=v;
    __syncthreads();
    if(warp==0){
        int w=ws[lane];
        #pragma unroll
        for(int o=1;o<32;o<<=1){int u=__shfl_up_sync(0xffffffffu,w,o);if(lane>=o)w+=u;}
        ws[lane]=w;
    }
    __syncthreads();
    int base=(warp?ws[warp-1]:0)+v-s3;
    ptr[4*t+1]=base+s0;ptr[4*t+2]=base+s1;ptr[4*t+3]=base+s2;ptr[4*t+4]=base+s3;
    if(t==0)ptr[0]=0;
}
__global__ void k_fillcsr(const int*src,const int*dst,int*cur,int*col,int*eid){
    int e=blockIdx.x*blockDim.x+threadIdx.x;
    if(e<EE){int d=dst[e];int p=atomicAdd(&cur[d],1);col[p]=src[e];eid[p]=e;}
}
__global__ void k_dinv(const int*cnt,float*d2,float*d1,float*cf){
    int i=blockIdx.x*blockDim.x+threadIdx.x;
    if(i<NN){float c=(float)cnt[i];d2[i]=rsqrtf(c+2.f);d1[i]=rsqrtf(c+1.f);cf[i]=c;}
}
__global__ void k_pnorm(const float*pw,float*pn){
    __shared__ float r[128]; int tid=threadIdx.x;
    for(int l=0;l<5;l++){
        float v=pw[l*128+tid];r[tid]=v*v;__syncthreads();
        for(int s=64;s>0;s>>=1){if(tid<s)r[tid]+=r[tid+s];__syncthreads();}
        if(tid==0)pn[l]=sqrtf(r[0]);
        __syncthreads();
    }
}

// ---- fused GEMM: C = rs ⊙ (op(A)@op(B) + fill*D) + bias, relu ----
// AM: 0 plain | 1 row-gather*scale | 2 row-add (pos/up) | 3 node-attr compose | 4 cat(H1,relu(UNET))
// BMo: 0 plain | 1 dual (gn<128 ? B : B2)
// Tile: TM x 64, micro WM x 4 per thread, THREADS=(TM/WM)*16=256 for all configs.
template<int AM,int BMo,int TM,int WM>
__global__ void __launch_bounds__((TM/WM)*16) k_gemmT(
        const float*__restrict__ A,const float*__restrict__ B,const float*__restrict__ B2,
        float*__restrict__ C,int M,int N,int K,
        const float*__restrict__ rs,const float*__restrict__ bias,int relu,
        const float*__restrict__ Dm,float fill,
        const int*__restrict__ aidx,const float*__restrict__ aux,const float*__restrict__ aux2){
    constexpr int THREADS=(TM/WM)*16;
    constexpr int AELEM=TM*16/THREADS;   // = WM
    constexpr int BELEM=1024/THREADS;
    __shared__ float As[16][TM+4];
    __shared__ float Bs[16][64];
    int tid=threadIdx.x;
    int tx=tid&15, ty=tid>>4;            // ty: 0..TM/WM-1
    int m0=blockIdx.y*TM, n0=blockIdx.x*64;
    float acc[WM][4]={};
    for(int k0=0;k0<K;k0+=16){
        #pragma unroll
        for(int l=0;l<AELEM;l++){
            int lin=tid+l*THREADS; int m=lin>>4, kk=lin&15;
            int gm=m0+m, gk=k0+kk; float v=0.f;
            if(gm<M&&gk<K){
                if(AM==0)v=A[gm*K+gk];
                else if(AM==1)v=A[aidx[gm]*K+gk]*aux[gm];
                else if(AM==2){v=A[gm*K+gk];int p=aidx[gm];if(p>=0)v+=aux[p*K+gk];}
                else if(AM==3)v=(gk<4)?A[gm*4+gk]:(gk<12?aux[gm*8+gk-4]:aux2[gm*128+gk-12]);
                else if(AM==4)v=(gk<128)?A[gm*128+gk]:fmaxf(aux[gm*128+gk-128],0.f);
            }
            As[kk][m]=v;
        }
        #pragma unroll
        for(int l=0;l<BELEM;l++){
            int lin=tid+l*THREADS; int kk=lin>>6, nn=lin&63;
            int gk=k0+kk, gn=n0+nn; float v=0.f;
            if(gk<K&&gn<N){
                if(BMo==0)v=B[gk*N+gn];
                else v=(gn<128)?B[gk*128+gn]:B2[gk*128+gn-128];
            }
            Bs[kk][nn]=v;
        }
        __syncthreads();
        #pragma unroll
        for(int kk=0;kk<16;kk++){
            float a[WM];
            #pragma unroll
            for(int i=0;i<WM;i++)a[i]=As[kk][ty*WM+i];
            float4 bv=*reinterpret_cast<const float4*>(&Bs[kk][tx*4]);
            float b[4]={bv.x,bv.y,bv.z,bv.w};
            #pragma unroll
            for(int i=0;i<WM;i++)
                #pragma unroll
                for(int j=0;j<4;j++)acc[i][j]+=a[i]*b[j];
        }
        __syncthreads();
    }
    #pragma unroll
    for(int i=0;i<WM;i++){
        int r=m0+ty*WM+i; if(r>=M)continue;
        float sc=rs?rs[r]:1.f;
        #pragma unroll
        for(int j=0;j<4;j++){
            int c=n0+tx*4+j; if(c>=N)continue;
            float v=acc[i][j];
            if(Dm)v+=fill*Dm[r*N+c];
            v*=sc;
            if(bias)v+=bias[c];
            if(relu)v=fmaxf(v,0.f);
            C[r*N+c]=v;
        }
    }
}

// message aggregation + relu(h1). P/Q packed in PQ (stride 256).
__global__ void k_h1m(const int*__restrict__ ptr,const int*__restrict__ col,
                      const int*__restrict__ eid,const float*__restrict__ me,
                      const float*__restrict__ Wm,const float*__restrict__ PQ,
                      const float*__restrict__ bm,const float*__restrict__ cf,float*h1){
    __shared__ float wb[512];
    int d=blockIdx.x,h=threadIdx.x;
    const float*Wb=Wm+280*128;
    for(int i=h;i<512;i+=128)wb[i]=Wb[i];
    __syncthreads();
    float s=0.f;
    int e0=ptr[d],e1=ptr[d+1];
    for(int i=e0;i<e1;i++){
        int c=col[i],e=eid[i];
        s+=PQ[c*256+128+h]+me[e*4]*wb[h]+me[e*4+1]*wb[128+h]+me[e*4+2]*wb[256+h]+me[e*4+3]*wb[384+h];
    }
    h1[d*128+h]=fmaxf(s+cf[d]*(PQ[d*256+h]+bm[h]),0.f);
}
// CSR spmm + gcn epilogue
__global__ void k_spmmgcn(const int*__restrict__ ptr,const int*__restrict__ col,
                          const float*__restrict__ z,const float*__restrict__ dinv,
                          const float*__restrict__ bias,float fill,int relu,float*out){
    int d=blockIdx.x,h=threadIdx.x;
    float s=0.f;
    int e0=ptr[d],e1=ptr[d+1];
    for(int i=e0;i<e1;i++)s+=z[col[i]*128+h];
    float v=dinv[d]*(s+fill*z[d*128+h])+bias[h];
    out[d*128+h]=relu?fmaxf(v,0.f):v;
}
// grid-parallel score
__global__ void k_score(const float*__restrict__ x,const float*__restrict__ w,
                        const float*__restrict__ pn,int l,float*sc){
    __shared__ float r[128]; int n=blockIdx.x,tid=threadIdx.x;
    r[tid]=x[n*128+tid]*w[tid];__syncthreads();
    for(int s=64;s>0;s>>=1){if(tid<s)r[tid]+=r[tid+s];__syncthreads();}
    if(tid==0)sc[n]=tanhf(r[0]/pn[l]);
}
// single-block bitonic sort + perm/sv/pos. desc by value, ties -> lower index.
__global__ void k_topk(const float*__restrict__ sc,int n,int pad,int k,
                       int*perm,float*sv,int*pos){
    __shared__ float v[4096]; __shared__ int id[4096];
    int tid=threadIdx.x;
    for(int i=tid;i<pad;i+=1024){v[i]=(i<n)?sc[i]:-3.4e38f;id[i]=(i<n)?i:0x7fffffff;}
    __syncthreads();
    for(int ks=2;ks<=pad;ks<<=1){
        for(int j=ks>>1;j>0;j>>=1){
            for(int i=tid;i<pad;i+=1024){
                int ixj=i^j;
                if(ixj>i){
                    bool up=((i&ks)==0);
                    float va=v[ixj],vb=v[i];int ia=id[ixj],ib=id[i];
                    bool pre=(va>vb)||(va==vb&&ia<ib);
                    if(pre==up){v[ixj]=vb;v[i]=va;id[ixj]=ib;id[i]=ia;}
                }
            }
            __syncthreads();
        }
    }
    for(int i=tid;i<pad;i+=1024){
        int d=id[i];
        if(i<k){perm[i]=d;sv[i]=v[i];}
        if(d<n)pos[d]=(i<k)?i:-1;
    }
}
// level-0 restricted augment: shared-row two-hop; fuses zero+atomics+diag+rowsum(pd)
__global__ void k_ap0(const int*__restrict__ perm,const int*__restrict__ ptr,
                      const int*__restrict__ col,const int*__restrict__ pos,
                      float*__restrict__ ap,float*__restrict__ pd){
    __shared__ float row[820];
    __shared__ float red[4];
    int a=blockIdx.x,pa=perm[a];
    int tid=threadIdx.x,lane=tid&31,warp=tid>>5;
    for(int b=tid;b<820;b+=128)row[b]=0.f;
    __syncthreads();
    int beg=ptr[pa],end=ptr[pa+1];
    for(int i1=beg+warp;i1<end;i1+=4){
        int c1=col[i1];
        if(c1==pa)continue;
        if(lane==0){int b=pos[c1];if(b>=0)atomicAdd(&row[b],2.f);}
        int b2=ptr[c1],e2=ptr[c1+1];
        for(int i2=b2+lane;i2<e2;i2+=32){
            int c2=col[i2];
            if(c2==c1)continue;
            int b=pos[c2];
            if(b>=0)atomicAdd(&row[b],1.f);
        }
    }
    __syncthreads();
    if(tid==0)row[a]=0.f;
    __syncthreads();
    float s=0.f;
    for(int b=tid;b<820;b+=128)s+=row[b];
    #pragma unroll
    for(int o=16;o>0;o>>=1)s+=__shfl_xor_sync(0xffffffffu,s,o);
    if(lane==0)red[warp]=s;
    __syncthreads();
    if(tid==0)pd[a]=rsqrtf(red[0]+red[1]+red[2]+red[3]+2.f);
    for(int b=tid;b<820;b+=128)ap[a*820+b]=row[b];
}
// L[m x n]: row a = A1[perm[a], :];  R[n x m]: col b = A1[:, perm[b]]
__global__ void k_gLR(const float*__restrict__ Ap,int n,const int*__restrict__ perm,int m,
                      float*__restrict__ L,float*__restrict__ R){
    int i=blockIdx.x*blockDim.x+threadIdx.x;
    if(i<m*n){int a=i/n,k=i-a*n;int pa=perm[a];L[i]=(k==pa)?1.f:Ap[pa*n+k];}
    if(i<n*m){int k=i/m,b=i-k*m;int pb=perm[b];R[i]=(k==pb)?1.f:Ap[k*n+pb];}
}
// zero diag + row-sum -> pd (levels >= 1)
__global__ void k_rowdinv(float*ap,int m,float*pd){
    int a=blockIdx.x*blockDim.x+threadIdx.x;
    if(a<m){
        ap[a*m+a]=0.f;
        float s=0.f;
        for(int b=0;b<m;b++)s+=ap[a*m+b];
        pd[a]=rsqrtf(s+2.f);
    }
}
__global__ void k_fout(const int*__restrict__ ptr,const int*__restrict__ col,
                       const float*__restrict__ z4,const float*__restrict__ d1,
                       const float*__restrict__ bo,float*Fb,float*out,int t){
    int i=blockIdx.x*blockDim.x+threadIdx.x;
    if(i<NN*4){int d=i>>2,f=i&3;
        float s=0.f;
        int e0=ptr[d],e1=ptr[d+1];
        for(int j=e0;j<e1;j++)s+=z4[col[j]*4+f];
        float v=d1[d]*(s+z4[i])+bo[f];
        Fb[i]=v;out[d*8+t*4+f]=v;}
}

// ---- host ----
template<int AM,int BMo>
static void gemmT(const float*A,const float*B,const float*B2,float*C,int M,int N,int K,
                  const float*rs,const float*bias,int relu,const float*Dm,float fill,
                  const int*aidx,const float*aux,const float*aux2){
    if(M>=1024){
        dim3 g(CDIV(N,64),CDIV(M,128));
        k_gemmT<AM,BMo,128,8><<<g,256>>>(A,B,B2,C,M,N,K,rs,bias,relu,Dm,fill,aidx,aux,aux2);
    }else if(M>=64){
        dim3 g(CDIV(N,64),CDIV(M,32));
        k_gemmT<AM,BMo,32,2><<<g,256>>>(A,B,B2,C,M,N,K,rs,bias,relu,Dm,fill,aidx,aux,aux2);
    }else{
        dim3 g(CDIV(N,64),CDIV(M,16));
        k_gemmT<AM,BMo,16,1><<<g,256>>>(A,B,B2,C,M,N,K,rs,bias,relu,Dm,fill,aidx,aux,aux2);
    }
}

extern "C" void kernel_launch(void* const* d_in, const int* in_sizes, int n_in,
                              void* d_out, int out_size){
    const float*F0 =(const float*)d_in[0];
    const float*mn =(const float*)d_in[1];
    const float*me =(const float*)d_in[2];
    const float*Wm =(const float*)d_in[3];
    const float*bm =(const float*)d_in[4];
    const float*Wd0=(const float*)d_in[5];
    const float*bd0=(const float*)d_in[6];
    const float*Wd =(const float*)d_in[7];
    const float*bd =(const float*)d_in[8];
    const float*pw =(const float*)d_in[9];
    const float*Wu =(const float*)d_in[10];
    const float*bu =(const float*)d_in[11];
    const float*Wo =(const float*)d_in[12];
    const float*bo =(const float*)d_in[13];
    const int*ei   =(const int*)d_in[14];
    const int*src=ei,*dst=ei+EE;
    float*out=(float*)d_out;

    float*buf;int*ib;
    cudaGetSymbolAddress((void**)&buf,g_buf);
    cudaGetSymbolAddress((void**)&ib,g_ibuf);

    const int NS[6]={4096,820,164,33,7,2};
    const int KL[5]={820,164,33,7,2};
    const int POFF[5]={0,820,984,1017,1024};       // perm / sv / pd offsets
    const int QOFF[5]={0,4096,4916,5080,5113};     // pos offsets
    const int PAD[5]={4096,1024,256,64,8};
    float* AP[5]={buf+O_AP0,buf+O_AP1,buf+O_AP2,buf+O_AP3,buf+O_AP4};
    float* XL[6]={buf+O_X0,buf+O_XS1,buf+O_XS2,buf+O_XS3,buf+O_XS4,buf+O_XBOT};
    float*PQ=buf+O_PQ,*H1=buf+O_H1,*Z=buf+O_Z;
    float*XP=buf+O_XP,*XB=buf+O_XB,*UNET=buf+O_UNET;
    float*FB=buf+O_F,*Z4=buf+O_Z4,*SC=buf+O_SC;
    float*SV=buf+O_SV,*PD=buf+O_PD,*D2=buf+O_DI2,*D1=buf+O_DI1,*CF=buf+O_CF,*PN=buf+O_PN;
    float*Lb=buf+O_L,*Rb=buf+O_R;
    int*PTR=ib+I_PTR,*COL=ib+I_COL,*EID=ib+I_EID,*CUR=ib+I_CUR,*CNT=ib+I_CNT,
       *PERM=ib+I_PERM,*POS=ib+I_POS;

    // one-time setup
    k_zero<<<CDIV(NN*128,256),256>>>(UNET,NN*128);
    k_iset<<<CDIV(NN,256),256>>>(CNT,NN,0);
    k_count<<<CDIV(EE,256),256>>>(dst,CNT);
    k_scan<<<1,1024>>>(CNT,PTR);
    k_icopy<<<CDIV(NN,256),256>>>(CUR,PTR,NN);
    k_fillcsr<<<CDIV(EE,256),256>>>(src,dst,CUR,COL,EID);
    k_dinv<<<CDIV(NN,256),256>>>(CNT,D2,D1,CF);
    k_pnorm<<<1,128>>>(pw,PN);

    for(int t=0;t<2;t++){
        const float*Fc=(t==0)?F0:FB;
        // fused node-attr compose + P|Q GEMM
        gemmT<3,1>(Fc,Wm,Wm+140*128,PQ,NN,256,140,0,0,0,0,0.f,0,mn,UNET);
        k_h1m<<<NN,128>>>(PTR,COL,EID,me,Wm,PQ,bm,CF,H1);
        // unet down-0 gcn (fill=2, relu)
        gemmT<0,0>(H1,Wd0,0,Z,NN,128,128,D2,0,0,0,0.f,0,0,0);
        k_spmmgcn<<<NN,128>>>(PTR,COL,Z,D2,bd0,2.f,1,XL[0]);
        // down levels
        for(int i=0;i<5;i++){
            int n=NS[i],k=KL[i];
            k_score<<<n,128>>>(XL[i],pw+i*128,PN,i,SC);
            k_topk<<<1,1024>>>(SC,n,PAD[i],k,PERM+POFF[i],SV+POFF[i],POS+QOFF[i]);
            if(i==0){
                k_ap0<<<820,128>>>(PERM,PTR,COL,POS,AP[0],PD);
            }else{
                k_gLR<<<CDIV(k*n,256),256>>>(AP[i-1],n,PERM+POFF[i],k,Lb,Rb);
                gemmT<0,0>(Lb,Rb,0,AP[i],k,k,n,0,0,0,0,0.f,0,0,0);
                k_rowdinv<<<CDIV(k,64),64>>>(AP[i],k,PD+POFF[i]);
            }
            // Z = PD ⊙ (gather(x)*sv @ Wd)
            gemmT<1,0>(XL[i],Wd+i*16384,0,Z,k,128,128,PD+POFF[i],0,0,0,0.f,
                       PERM+POFF[i],SV+POFF[i],0);
            // x_{i+1} = relu(PD ⊙ (AP@Z + 2Z) + bd)
            gemmT<0,0>(AP[i],Z,0,XL[i+1],k,128,k,PD+POFF[i],bd+i*128,1,Z,2.f,0,0,0);
        }
        // up levels
        float*xin=XL[5];
        for(int i=0;i<5;i++){
            int j=4-i;
            if(j>0){
                int nj=NS[j];
                gemmT<2,0>(XL[j],Wu+i*16384,0,Z,nj,128,128,PD+POFF[j-1],0,0,0,0.f,
                           POS+QOFF[j],xin,0);
                float*xo=(i%2==0)?XB:XP;
                gemmT<0,0>(AP[j-1],Z,0,xo,nj,128,nj,PD+POFF[j-1],bu+i*128,1,Z,2.f,0,0,0);
                xin=xo;
            }else{
                gemmT<2,0>(XL[0],Wu+4*16384,0,Z,NN,128,128,D2,0,0,0,0.f,POS,xin,0);
                k_spmmgcn<<<NN,128>>>(PTR,COL,Z,D2,bu+4*128,2.f,0,UNET);
            }
        }
        // output gcn (fill=1), cat fused into A loader
        gemmT<4,0>(H1,Wo,0,Z4,NN,4,256,D1,0,0,0,0.f,0,UNET,0);
        k_fout<<<CDIV(NN*4,256),256>>>(PTR,COL,Z4,D1,bo,FB,out,t);
    }
}